// round 2
// baseline (speedup 1.0000x reference)
#include <cuda_runtime.h>
#include <cuda_bf16.h>
#include <cstddef>

// Problem constants: N=100000, E=1000000, F=64, H=8, D=8
#define MAXN 100000
#define CLIPV 5.0f
#define INV_SQRT_D 0.35355339059327373f
#define STR 68   // padded smem row stride (floats): conflict-free for frag loads

// ---------------- scratch (device globals) -----------------------------------
__device__ float g_Q[(size_t)MAXN * 64];
__device__ float g_K[(size_t)MAXN * 64];
__device__ float g_V[(size_t)MAXN * 64];
// per-node accumulator: 64 floats wV + 8 floats z, stride 72 (288B)
__device__ float g_acc[(size_t)MAXN * 72];

// ---------------- helpers ----------------------------------------------------
__device__ __forceinline__ float clipf(float x) {
    return fminf(fmaxf(x, -CLIPV), CLIPV);
}
__device__ __forceinline__ void red4(float* p, float a, float b, float c, float d) {
    asm volatile("red.global.add.v4.f32 [%0], {%1, %2, %3, %4};"
                 :: "l"(p), "f"(a), "f"(b), "f"(c), "f"(d) : "memory");
}
// split a float pair into bf16-hi pair and bf16-lo (residual) pair, packed
__device__ __forceinline__ void split2(float x0, float x1, unsigned& hi, unsigned& lo) {
    __nv_bfloat16 h0 = __float2bfloat16_rn(x0);
    __nv_bfloat16 h1 = __float2bfloat16_rn(x1);
    float r0 = x0 - __bfloat162float(h0);
    float r1 = x1 - __bfloat162float(h1);
    __nv_bfloat162 H; H.x = h0; H.y = h1;
    __nv_bfloat162 L; L.x = __float2bfloat16_rn(r0); L.y = __float2bfloat16_rn(r1);
    hi = *reinterpret_cast<unsigned*>(&H);
    lo = *reinterpret_cast<unsigned*>(&L);
}
__device__ __forceinline__ void mma_bf16(float c[4], const unsigned a[4], const unsigned b[2]) {
    asm volatile(
        "mma.sync.aligned.m16n8k16.row.col.f32.bf16.bf16.f32 "
        "{%0,%1,%2,%3}, {%4,%5,%6,%7}, {%8,%9}, {%0,%1,%2,%3};"
        : "+f"(c[0]), "+f"(c[1]), "+f"(c[2]), "+f"(c[3])
        : "r"(a[0]), "r"(a[1]), "r"(a[2]), "r"(a[3]), "r"(b[0]), "r"(b[1]));
}
// load one m16k64 A slice (bf16 hi/lo fragments) from smem tile row base R
__device__ __forceinline__ void load_a_frags(const float* sT, int R, int lq, int lr,
                                             unsigned ah[4][4], unsigned al[4][4]) {
    #pragma unroll
    for (int k = 0; k < 4; k++) {
        const float* base = sT + (size_t)(R + lq) * STR + 16 * k + 2 * lr;
        float2 q0 = *reinterpret_cast<const float2*>(base);
        float2 q1 = *reinterpret_cast<const float2*>(base + 8 * STR);
        float2 q2 = *reinterpret_cast<const float2*>(base + 8);
        float2 q3 = *reinterpret_cast<const float2*>(base + 8 * STR + 8);
        split2(q0.x, q0.y, ah[k][0], al[k][0]);
        split2(q1.x, q1.y, ah[k][1], al[k][1]);
        split2(q2.x, q2.y, ah[k][2], al[k][2]);
        split2(q3.x, q3.y, ah[k][3], al[k][3]);
    }
}

// ---------------- kernel 1: node projections Q,K,V (tensor-core) -------------
// block: 256 threads, 128 nodes. smem: x tile [128][STR] + W [192][STR].
// warp w owns n-tiles {3w, 3w+1, 3w+2} of 24 (Q:0-7, K:8-15, V:16-23),
// loops all 8 m-tiles; B fragments register-resident.
__global__ __launch_bounds__(256)
void node_mma_kernel(const float* __restrict__ nf,
                     const float* __restrict__ Wq, const float* __restrict__ bq,
                     const float* __restrict__ Wk, const float* __restrict__ bk,
                     const float* __restrict__ Wv, const float* __restrict__ bv,
                     int N) {
    extern __shared__ float smem[];
    float* sX = smem;               // [128][STR]
    float* sW = smem + 128 * STR;   // [192][STR]

    int tid = threadIdx.x;
    long nBase = (long)blockIdx.x * 128;

    for (int i = tid; i < 4096; i += 256) {
        int r = i >> 6, c = i & 63;
        sW[(size_t)r * STR + c]         = Wq[i];
        sW[(size_t)(64 + r) * STR + c]  = Wk[i];
        sW[(size_t)(128 + r) * STR + c] = Wv[i];
    }
    for (int i = tid; i < 128 * 16; i += 256) {
        int r = i >> 4, c4 = i & 15;
        long nn = nBase + r;
        float4 v = make_float4(0.f, 0.f, 0.f, 0.f);
        if (nn < N) v = *reinterpret_cast<const float4*>(nf + nn * 64 + c4 * 4);
        *reinterpret_cast<float4*>(sX + (size_t)r * STR + c4 * 4) = v;
    }
    __syncthreads();

    int w = tid >> 5, l = tid & 31;
    int lq = l >> 2, lr = l & 3;

    // B fragments for 3 n-tiles x 4 k-tiles (hi/lo)
    unsigned bh[3][4][2], bl[3][4][2];
    #pragma unroll
    for (int t = 0; t < 3; t++) {
        int n = 8 * (3 * w + t) + lq;   // row in sW [0,192)
        #pragma unroll
        for (int k = 0; k < 4; k++) {
            float2 p0 = *reinterpret_cast<const float2*>(sW + (size_t)n * STR + 16 * k + 2 * lr);
            float2 p1 = *reinterpret_cast<const float2*>(sW + (size_t)n * STR + 16 * k + 2 * lr + 8);
            split2(p0.x, p0.y, bh[t][k][0], bl[t][k][0]);
            split2(p1.x, p1.y, bh[t][k][1], bl[t][k][1]);
        }
    }

    float* gq = g_Q; float* gk = g_K; float* gv = g_V;

    #pragma unroll 1
    for (int mt = 0; mt < 8; mt++) {
        int R = 16 * mt;
        unsigned ah[4][4], al[4][4];
        load_a_frags(sX, R, lq, lr, ah, al);

        #pragma unroll
        for (int t = 0; t < 3; t++) {
            float acc[4] = {0.f, 0.f, 0.f, 0.f};
            #pragma unroll
            for (int k = 0; k < 4; k++) {
                mma_bf16(acc, ah[k], bh[t][k]);
                mma_bf16(acc, ah[k], bl[t][k]);
                mma_bf16(acc, al[k], bh[t][k]);
            }
            int g = 3 * w + t;
            int which = g >> 3;
            int colBase = 8 * (g & 7) + 2 * lr;
            float* outp = (which == 0) ? gq : (which == 1) ? gk : gv;
            const float* bp = (which == 0) ? bq : (which == 1) ? bk : bv;
            float2 bb = __ldg(reinterpret_cast<const float2*>(bp + colBase));
            long n0 = nBase + R + lq;
            long n1 = n0 + 8;
            if (n0 < N) {
                *reinterpret_cast<float2*>(outp + n0 * 64 + colBase) =
                    make_float2(acc[0] + bb.x, acc[1] + bb.y);
            }
            if (n1 < N) {
                *reinterpret_cast<float2*>(outp + n1 * 64 + colBase) =
                    make_float2(acc[2] + bb.x, acc[3] + bb.y);
            }
        }
    }
}

// ---------------- kernel 2: edge kernel (tensor-core proj + fused epilogue) --
// block: 256 threads, 128 edges. smem: ef/P tile [128][STR] + We [64][STR].
// GEMM: warp w -> m-tile pair (w&3), n-half (w>>2); P overwrites ef in place
// (sync between A-load and P-store protects the warp sharing the rows).
// Epilogue: 2 threads per edge, 4 heads each (heads are independent).
__global__ __launch_bounds__(256)
void edge_mma_kernel(const float* __restrict__ ef,
                     const int* __restrict__ src, const int* __restrict__ dst,
                     const float* __restrict__ We, const float* __restrict__ be,
                     float* __restrict__ e_out, int E) {
    extern __shared__ float smem[];
    float* sT = smem;               // ef tile, later P tile [128][STR]
    float* sW = smem + 128 * STR;   // We [64][STR]

    int tid = threadIdx.x;
    long eBase = (long)blockIdx.x * 128;

    for (int i = tid; i < 4096; i += 256) {
        int r = i >> 6, c = i & 63;
        sW[(size_t)r * STR + c] = We[i];
    }
    for (int i = tid; i < 128 * 16; i += 256) {
        int r = i >> 4, c4 = i & 15;
        long e = eBase + r;
        float4 v = make_float4(0.f, 0.f, 0.f, 0.f);
        if (e < E) v = *reinterpret_cast<const float4*>(ef + e * 64 + c4 * 4);
        *reinterpret_cast<float4*>(sT + (size_t)r * STR + c4 * 4) = v;
    }
    __syncthreads();

    int w = tid >> 5, l = tid & 31;
    int lq = l >> 2, lr = l & 3;
    int nhalf = w >> 2;     // 0..1 : cols 0-31 / 32-63
    int mpair = w & 3;      // 0..3 : m-tiles {2*mpair, 2*mpair+1}

    // B fragments: 4 n-tiles x 4 k-tiles (hi/lo)
    unsigned bh[4][4][2], bl[4][4][2];
    #pragma unroll
    for (int t = 0; t < 4; t++) {
        int n = 8 * (4 * nhalf + t) + lq;
        #pragma unroll
        for (int k = 0; k < 4; k++) {
            float2 p0 = *reinterpret_cast<const float2*>(sW + (size_t)n * STR + 16 * k + 2 * lr);
            float2 p1 = *reinterpret_cast<const float2*>(sW + (size_t)n * STR + 16 * k + 2 * lr + 8);
            split2(p0.x, p0.y, bh[t][k][0], bl[t][k][0]);
            split2(p1.x, p1.y, bh[t][k][1], bl[t][k][1]);
        }
    }

    #pragma unroll 1
    for (int mt = 0; mt < 2; mt++) {
        int R = 16 * (2 * mpair + mt);
        unsigned ah[4][4], al[4][4];
        load_a_frags(sT, R, lq, lr, ah, al);
        // both warps sharing these rows must finish A-loads before P overwrite
        __syncthreads();

        #pragma unroll
        for (int t = 0; t < 4; t++) {
            float acc[4] = {0.f, 0.f, 0.f, 0.f};
            #pragma unroll
            for (int k = 0; k < 4; k++) {
                mma_bf16(acc, ah[k], bh[t][k]);
                mma_bf16(acc, ah[k], bl[t][k]);
                mma_bf16(acc, al[k], bh[t][k]);
            }
            int colBase = 8 * (4 * nhalf + t) + 2 * lr;
            *reinterpret_cast<float2*>(sT + (size_t)(R + lq) * STR + colBase) =
                make_float2(acc[0], acc[1]);
            *reinterpret_cast<float2*>(sT + (size_t)(R + 8 + lq) * STR + colBase) =
                make_float2(acc[2], acc[3]);
        }
    }
    __syncthreads();

    // ---- epilogue: 2 threads per edge; thread handles heads 4*half..4*half+3
    int e_loc = tid >> 1, half = tid & 1;
    long e = eBase + e_loc;
    if (e < E) {
        int s = src[e], d = dst[e];

        const float4* Kp = reinterpret_cast<const float4*>(g_K + (size_t)s * 64 + 32 * half);
        const float4* Qp = reinterpret_cast<const float4*>(g_Q + (size_t)d * 64 + 32 * half);
        float sc[4];
        #pragma unroll
        for (int h = 0; h < 4; h++) {
            float4 k0 = Kp[2 * h], k1 = Kp[2 * h + 1];
            float4 q0 = Qp[2 * h], q1 = Qp[2 * h + 1];
            float acc = k0.x * q0.x + k0.y * q0.y + k0.z * q0.z + k0.w * q0.w
                      + k1.x * q1.x + k1.y * q1.y + k1.z * q1.z + k1.w * q1.w;
            sc[h] = clipf(acc * INV_SQRT_D);
        }

        const float* Prow = sT + (size_t)e_loc * STR + 32 * half;
        const float* beP = be + 32 * half;
        float* eo = e_out + (size_t)e * 64 + 32 * half;
        float ssum[4] = {0.f, 0.f, 0.f, 0.f};
        #pragma unroll
        for (int i = 0; i < 8; i++) {
            float4 p = *reinterpret_cast<const float4*>(Prow + 4 * i);
            float4 b = __ldg(reinterpret_cast<const float4*>(beP + 4 * i));
            float s0 = sc[i >> 1];
            float4 r;
            r.x = s0 * (p.x + b.x); r.y = s0 * (p.y + b.y);
            r.z = s0 * (p.z + b.z); r.w = s0 * (p.w + b.w);
            ssum[i >> 1] += (r.x + r.y) + (r.z + r.w);
            *reinterpret_cast<float4*>(eo + 4 * i) = r;
        }

        float wv[4];
        #pragma unroll
        for (int h = 0; h < 4; h++) wv[h] = __expf(clipf(ssum[h]));

        const float4* Vp = reinterpret_cast<const float4*>(g_V + (size_t)s * 64 + 32 * half);
        float* ap = g_acc + (size_t)d * 72 + 32 * half;
        #pragma unroll
        for (int i = 0; i < 8; i++) {
            float4 v = Vp[i];
            float wh = wv[i >> 1];
            red4(ap + 4 * i, v.x * wh, v.y * wh, v.z * wh, v.w * wh);
        }
        red4(g_acc + (size_t)d * 72 + 64 + 4 * half, wv[0], wv[1], wv[2], wv[3]);
    }
}

// ---------------- kernel 3: finalize h_out = wV / (z + 1e-6) -----------------
__global__ __launch_bounds__(256)
void finalize_kernel(float* __restrict__ h_out, int N) {
    int t = blockIdx.x * 256 + threadIdx.x;
    if (t >= N * 16) return;
    int n = t >> 4, g = t & 15;
    const float* ap = g_acc + (size_t)n * 72;
    float4 wv = *reinterpret_cast<const float4*>(ap + 4 * g);
    float z = ap[64 + (g >> 1)];
    float inv = 1.0f / (z + 1e-6f);
    float4 r;
    r.x = wv.x * inv; r.y = wv.y * inv; r.z = wv.z * inv; r.w = wv.w * inv;
    *reinterpret_cast<float4*>(h_out + (size_t)n * 64 + 4 * g) = r;
}

// ---------------- launch ------------------------------------------------------
extern "C" void kernel_launch(void* const* d_in, const int* in_sizes, int n_in,
                              void* d_out, int out_size) {
    const float* nf = (const float*)d_in[0];
    const float* ef = (const float*)d_in[1];
    const int*   src = (const int*)d_in[2];
    const int*   dst = (const int*)d_in[3];
    const float* Wq = (const float*)d_in[4];
    const float* bq = (const float*)d_in[5];
    const float* Wk = (const float*)d_in[6];
    const float* bk = (const float*)d_in[7];
    const float* Wv = (const float*)d_in[8];
    const float* bv = (const float*)d_in[9];
    const float* We = (const float*)d_in[10];
    const float* be = (const float*)d_in[11];

    int N = in_sizes[0] / 64;
    int E = in_sizes[2];

    float* h_out = (float*)d_out;                  // [N, 64]
    float* e_out = (float*)d_out + (size_t)N * 64; // [E, 64]

    const int NODE_SMEM = (128 + 192) * STR * 4;   // 87040
    const int EDGE_SMEM = (128 + 64) * STR * 4;    // 52224
    cudaFuncSetAttribute(node_mma_kernel,
                         cudaFuncAttributeMaxDynamicSharedMemorySize, NODE_SMEM);
    cudaFuncSetAttribute(edge_mma_kernel,
                         cudaFuncAttributeMaxDynamicSharedMemorySize, EDGE_SMEM);

    void* accp = nullptr;
    cudaGetSymbolAddress(&accp, g_acc);
    cudaMemsetAsync(accp, 0, (size_t)N * 72 * sizeof(float));

    node_mma_kernel<<<(N + 127) / 128, 256, NODE_SMEM>>>(nf, Wq, bq, Wk, bk, Wv, bv, N);
    edge_mma_kernel<<<(E + 127) / 128, 256, EDGE_SMEM>>>(ef, src, dst, We, be, e_out, E);
    finalize_kernel<<<((N * 16) + 255) / 256, 256>>>(h_out, N);
}

// round 3
// speedup vs baseline: 1.2969x; 1.2969x over previous
#include <cuda_runtime.h>
#include <cuda_bf16.h>
#include <cstddef>

// Problem constants: N=100000, E=1000000, F=64, H=8, D=8
#define MAXN 100000
#define CLIPV 5.0f
#define INV_SQRT_D 0.35355339059327373f
#define STR 68   // padded smem row stride (floats)

// ---------------- scratch (device globals) -----------------------------------
__device__ float g_Q[(size_t)MAXN * 64];
__device__ float g_K[(size_t)MAXN * 64];
__device__ float g_V[(size_t)MAXN * 64];
// per-node accumulator: 64 floats wV + 8 floats z, stride 72 (288B)
__device__ float g_acc[(size_t)MAXN * 72];

// ---------------- helpers ----------------------------------------------------
__device__ __forceinline__ float clipf(float x) {
    return fminf(fmaxf(x, -CLIPV), CLIPV);
}
__device__ __forceinline__ void red4(float* p, float a, float b, float c, float d) {
    asm volatile("red.global.add.v4.f32 [%0], {%1, %2, %3, %4};"
                 :: "l"(p), "f"(a), "f"(b), "f"(c), "f"(d) : "memory");
}
__device__ __forceinline__ void red1(float* p, float v) {
    asm volatile("red.global.add.f32 [%0], %1;" :: "l"(p), "f"(v) : "memory");
}
// split a float pair into bf16-hi pair and bf16-lo (residual) pair, packed
__device__ __forceinline__ void split2(float x0, float x1, unsigned& hi, unsigned& lo) {
    __nv_bfloat16 h0 = __float2bfloat16_rn(x0);
    __nv_bfloat16 h1 = __float2bfloat16_rn(x1);
    float r0 = x0 - __bfloat162float(h0);
    float r1 = x1 - __bfloat162float(h1);
    __nv_bfloat162 H; H.x = h0; H.y = h1;
    __nv_bfloat162 L; L.x = __float2bfloat16_rn(r0); L.y = __float2bfloat16_rn(r1);
    hi = *reinterpret_cast<unsigned*>(&H);
    lo = *reinterpret_cast<unsigned*>(&L);
}
__device__ __forceinline__ void mma_bf16(float c[4], const unsigned a[4], const unsigned b[2]) {
    asm volatile(
        "mma.sync.aligned.m16n8k16.row.col.f32.bf16.bf16.f32 "
        "{%0,%1,%2,%3}, {%4,%5,%6,%7}, {%8,%9}, {%0,%1,%2,%3};"
        : "+f"(c[0]), "+f"(c[1]), "+f"(c[2]), "+f"(c[3])
        : "r"(a[0]), "r"(a[1]), "r"(a[2]), "r"(a[3]), "r"(b[0]), "r"(b[1]));
}
// load one m16k64 A slice (bf16 hi/lo fragments) from smem tile row base R
__device__ __forceinline__ void load_a_frags(const float* sT, int R, int lq, int lr,
                                             unsigned ah[4][4], unsigned al[4][4]) {
    #pragma unroll
    for (int k = 0; k < 4; k++) {
        const float* base = sT + (size_t)(R + lq) * STR + 16 * k + 2 * lr;
        float2 q0 = *reinterpret_cast<const float2*>(base);
        float2 q1 = *reinterpret_cast<const float2*>(base + 8 * STR);
        float2 q2 = *reinterpret_cast<const float2*>(base + 8);
        float2 q3 = *reinterpret_cast<const float2*>(base + 8 * STR + 8);
        split2(q0.x, q0.y, ah[k][0], al[k][0]);
        split2(q1.x, q1.y, ah[k][1], al[k][1]);
        split2(q2.x, q2.y, ah[k][2], al[k][2]);
        split2(q3.x, q3.y, ah[k][3], al[k][3]);
    }
}

// ---------------- kernel 1: node projections Q,K,V (tensor-core) + acc zero --
__global__ __launch_bounds__(256)
void node_mma_kernel(const float* __restrict__ nf,
                     const float* __restrict__ Wq, const float* __restrict__ bq,
                     const float* __restrict__ Wk, const float* __restrict__ bk,
                     const float* __restrict__ Wv, const float* __restrict__ bv,
                     int N) {
    extern __shared__ float smem[];
    float* sX = smem;               // [128][STR]
    float* sW = smem + 128 * STR;   // [192][STR]

    int tid = threadIdx.x;
    long nBase = (long)blockIdx.x * 128;

    // zero g_acc (grid-stride, vectorized) — replaces the separate memset
    {
        float4 z4 = make_float4(0.f, 0.f, 0.f, 0.f);
        float4* ap = reinterpret_cast<float4*>(g_acc);
        long total4 = (long)N * 18;  // N*72/4
        for (long i = (long)blockIdx.x * 256 + tid; i < total4; i += (long)gridDim.x * 256)
            ap[i] = z4;
    }

    for (int i = tid; i < 4096; i += 256) {
        int r = i >> 6, c = i & 63;
        sW[(size_t)r * STR + c]         = Wq[i];
        sW[(size_t)(64 + r) * STR + c]  = Wk[i];
        sW[(size_t)(128 + r) * STR + c] = Wv[i];
    }
    for (int i = tid; i < 128 * 16; i += 256) {
        int r = i >> 4, c4 = i & 15;
        long nn = nBase + r;
        float4 v = make_float4(0.f, 0.f, 0.f, 0.f);
        if (nn < N) v = *reinterpret_cast<const float4*>(nf + nn * 64 + c4 * 4);
        *reinterpret_cast<float4*>(sX + (size_t)r * STR + c4 * 4) = v;
    }
    __syncthreads();

    int w = tid >> 5, l = tid & 31;
    int lq = l >> 2, lr = l & 3;

    unsigned bh[3][4][2], bl[3][4][2];
    #pragma unroll
    for (int t = 0; t < 3; t++) {
        int n = 8 * (3 * w + t) + lq;
        #pragma unroll
        for (int k = 0; k < 4; k++) {
            float2 p0 = *reinterpret_cast<const float2*>(sW + (size_t)n * STR + 16 * k + 2 * lr);
            float2 p1 = *reinterpret_cast<const float2*>(sW + (size_t)n * STR + 16 * k + 2 * lr + 8);
            split2(p0.x, p0.y, bh[t][k][0], bl[t][k][0]);
            split2(p1.x, p1.y, bh[t][k][1], bl[t][k][1]);
        }
    }

    #pragma unroll 1
    for (int mt = 0; mt < 8; mt++) {
        int R = 16 * mt;
        unsigned ah[4][4], al[4][4];
        load_a_frags(sX, R, lq, lr, ah, al);

        #pragma unroll
        for (int t = 0; t < 3; t++) {
            float acc[4] = {0.f, 0.f, 0.f, 0.f};
            #pragma unroll
            for (int k = 0; k < 4; k++) {
                mma_bf16(acc, ah[k], bh[t][k]);
                mma_bf16(acc, ah[k], bl[t][k]);
                mma_bf16(acc, al[k], bh[t][k]);
            }
            int g = 3 * w + t;
            int which = g >> 3;
            int colBase = 8 * (g & 7) + 2 * lr;
            float* outp = (which == 0) ? g_Q : (which == 1) ? g_K : g_V;
            const float* bp = (which == 0) ? bq : (which == 1) ? bk : bv;
            float2 bb = __ldg(reinterpret_cast<const float2*>(bp + colBase));
            long n0 = nBase + R + lq;
            long n1 = n0 + 8;
            if (n0 < N)
                *reinterpret_cast<float2*>(outp + n0 * 64 + colBase) =
                    make_float2(acc[0] + bb.x, acc[1] + bb.y);
            if (n1 < N)
                *reinterpret_cast<float2*>(outp + n1 * 64 + colBase) =
                    make_float2(acc[2] + bb.x, acc[3] + bb.y);
        }
    }
}

// ---------------- kernel 2: edge kernel --------------------------------------
// GEMM part identical to round 2 (P tile in smem, in-place over ef tile).
// Epilogue restructured: lane = (edge, head). 8 consecutive lanes = 8 heads of
// one edge -> K/Q/V gathers are 64B-contiguous per edge (coalesced), the
// red-scatter per edge is a contiguous 288B burst. Streaming hints (.cs) on
// ef / src / dst / e_out keep Q/K/V/g_acc resident in L2.
__global__ __launch_bounds__(256)
void edge_mma_kernel(const float* __restrict__ ef,
                     const int* __restrict__ src, const int* __restrict__ dst,
                     const float* __restrict__ We, const float* __restrict__ be,
                     float* __restrict__ e_out, int E) {
    extern __shared__ float smem[];
    float* sT = smem;               // ef tile, later P tile [128][STR]
    float* sW = smem + 128 * STR;   // We [64][STR]

    int tid = threadIdx.x;
    long eBase = (long)blockIdx.x * 128;

    for (int i = tid; i < 4096; i += 256) {
        int r = i >> 6, c = i & 63;
        sW[(size_t)r * STR + c] = We[i];
    }
    for (int i = tid; i < 128 * 16; i += 256) {
        int r = i >> 4, c4 = i & 15;
        long e = eBase + r;
        float4 v = make_float4(0.f, 0.f, 0.f, 0.f);
        if (e < E) v = __ldcs(reinterpret_cast<const float4*>(ef + e * 64 + c4 * 4));
        *reinterpret_cast<float4*>(sT + (size_t)r * STR + c4 * 4) = v;
    }
    __syncthreads();

    int w = tid >> 5, l = tid & 31;
    int lq = l >> 2, lr = l & 3;
    int nhalf = w >> 2;
    int mpair = w & 3;

    unsigned bh[4][4][2], bl[4][4][2];
    #pragma unroll
    for (int t = 0; t < 4; t++) {
        int n = 8 * (4 * nhalf + t) + lq;
        #pragma unroll
        for (int k = 0; k < 4; k++) {
            float2 p0 = *reinterpret_cast<const float2*>(sW + (size_t)n * STR + 16 * k + 2 * lr);
            float2 p1 = *reinterpret_cast<const float2*>(sW + (size_t)n * STR + 16 * k + 2 * lr + 8);
            split2(p0.x, p0.y, bh[t][k][0], bl[t][k][0]);
            split2(p1.x, p1.y, bh[t][k][1], bl[t][k][1]);
        }
    }

    #pragma unroll 1
    for (int mt = 0; mt < 2; mt++) {
        int R = 16 * (2 * mpair + mt);
        unsigned ah[4][4], al[4][4];
        load_a_frags(sT, R, lq, lr, ah, al);
        __syncthreads();   // all A-loads done before P overwrite

        #pragma unroll
        for (int t = 0; t < 4; t++) {
            float acc[4] = {0.f, 0.f, 0.f, 0.f};
            #pragma unroll
            for (int k = 0; k < 4; k++) {
                mma_bf16(acc, ah[k], bh[t][k]);
                mma_bf16(acc, ah[k], bl[t][k]);
                mma_bf16(acc, al[k], bh[t][k]);
            }
            int colBase = 8 * (4 * nhalf + t) + 2 * lr;
            *reinterpret_cast<float2*>(sT + (size_t)(R + lq) * STR + colBase) =
                make_float2(acc[0], acc[1]);
            *reinterpret_cast<float2*>(sT + (size_t)(R + 8 + lq) * STR + colBase) =
                make_float2(acc[2], acc[3]);
        }
    }
    __syncthreads();

    // ---- epilogue: lane = (edge, head); 4 passes of 32 edges ----------------
    int h = tid & 7;           // head 0..7
    int eg = tid >> 3;         // 0..31
    #pragma unroll 1
    for (int sub = 0; sub < 4; sub++) {
        int e_loc = sub * 32 + eg;
        long e = eBase + e_loc;
        if (e >= E) break;

        int s = __ldcs(src + e);
        int d = __ldcs(dst + e);

        // score for this head: 64B-contiguous gathers per edge across 8 lanes
        const float4* Kp = reinterpret_cast<const float4*>(g_K + (size_t)s * 64 + 8 * h);
        const float4* Qp = reinterpret_cast<const float4*>(g_Q + (size_t)d * 64 + 8 * h);
        float4 k0 = Kp[0], k1 = Kp[1];
        float4 q0 = Qp[0], q1 = Qp[1];
        float sc = k0.x * q0.x + k0.y * q0.y + k0.z * q0.z + k0.w * q0.w
                 + k1.x * q1.x + k1.y * q1.y + k1.z * q1.z + k1.w * q1.w;
        sc = clipf(sc * INV_SQRT_D);

        // P row (smem) + bias, scale by score, write e_out, row-sum
        const float* Prow = sT + (size_t)e_loc * STR + 8 * h;
        float4 p0 = *reinterpret_cast<const float4*>(Prow);
        float4 p1 = *reinterpret_cast<const float4*>(Prow + 4);
        float4 b0 = __ldg(reinterpret_cast<const float4*>(be + 8 * h));
        float4 b1 = __ldg(reinterpret_cast<const float4*>(be + 8 * h + 4));
        float4 r0, r1;
        r0.x = sc * (p0.x + b0.x); r0.y = sc * (p0.y + b0.y);
        r0.z = sc * (p0.z + b0.z); r0.w = sc * (p0.w + b0.w);
        r1.x = sc * (p1.x + b1.x); r1.y = sc * (p1.y + b1.y);
        r1.z = sc * (p1.z + b1.z); r1.w = sc * (p1.w + b1.w);
        float ssum = ((r0.x + r0.y) + (r0.z + r0.w)) + ((r1.x + r1.y) + (r1.z + r1.w));
        __stcs(reinterpret_cast<float4*>(e_out + (size_t)e * 64 + 8 * h), r0);
        __stcs(reinterpret_cast<float4*>(e_out + (size_t)e * 64 + 8 * h + 4), r1);

        float wv = __expf(clipf(ssum));

        // scatter: contiguous 288B burst per edge across its 8 lanes
        const float4* Vp = reinterpret_cast<const float4*>(g_V + (size_t)s * 64 + 8 * h);
        float4 v0 = Vp[0], v1 = Vp[1];
        float* ap = g_acc + (size_t)d * 72 + 8 * h;
        red4(ap,     v0.x * wv, v0.y * wv, v0.z * wv, v0.w * wv);
        red4(ap + 4, v1.x * wv, v1.y * wv, v1.z * wv, v1.w * wv);
        red1(g_acc + (size_t)d * 72 + 64 + h, wv);
    }
}

// ---------------- kernel 3: finalize h_out = wV / (z + 1e-6) -----------------
__global__ __launch_bounds__(256)
void finalize_kernel(float* __restrict__ h_out, int N) {
    int t = blockIdx.x * 256 + threadIdx.x;
    if (t >= N * 16) return;
    int n = t >> 4, g = t & 15;
    const float* ap = g_acc + (size_t)n * 72;
    float4 wv = *reinterpret_cast<const float4*>(ap + 4 * g);
    float z = ap[64 + (g >> 1)];
    float inv = 1.0f / (z + 1e-6f);
    float4 r;
    r.x = wv.x * inv; r.y = wv.y * inv; r.z = wv.z * inv; r.w = wv.w * inv;
    __stcs(reinterpret_cast<float4*>(h_out + (size_t)n * 64 + 4 * g), r);
}

// dummy launch to align ncu's skip-5 capture onto the edge kernel
__global__ void pad_kernel() {}

// ---------------- launch ------------------------------------------------------
extern "C" void kernel_launch(void* const* d_in, const int* in_sizes, int n_in,
                              void* d_out, int out_size) {
    const float* nf = (const float*)d_in[0];
    const float* ef = (const float*)d_in[1];
    const int*   src = (const int*)d_in[2];
    const int*   dst = (const int*)d_in[3];
    const float* Wq = (const float*)d_in[4];
    const float* bq = (const float*)d_in[5];
    const float* Wk = (const float*)d_in[6];
    const float* bk = (const float*)d_in[7];
    const float* Wv = (const float*)d_in[8];
    const float* bv = (const float*)d_in[9];
    const float* We = (const float*)d_in[10];
    const float* be = (const float*)d_in[11];

    int N = in_sizes[0] / 64;
    int E = in_sizes[2];

    float* h_out = (float*)d_out;                  // [N, 64]
    float* e_out = (float*)d_out + (size_t)N * 64; // [E, 64]

    const int NODE_SMEM = (128 + 192) * STR * 4;   // 87040
    const int EDGE_SMEM = (128 + 64) * STR * 4;    // 52224
    cudaFuncSetAttribute(node_mma_kernel,
                         cudaFuncAttributeMaxDynamicSharedMemorySize, NODE_SMEM);
    cudaFuncSetAttribute(edge_mma_kernel,
                         cudaFuncAttributeMaxDynamicSharedMemorySize, EDGE_SMEM);

    node_mma_kernel<<<(N + 127) / 128, 256, NODE_SMEM>>>(nf, Wq, bq, Wk, bk, Wv, bv, N);
    edge_mma_kernel<<<(E + 127) / 128, 256, EDGE_SMEM>>>(ef, src, dst, We, be, e_out, E);
    finalize_kernel<<<((N * 16) + 255) / 256, 256>>>(h_out, N);
    pad_kernel<<<1, 32>>>();
}

// round 4
// speedup vs baseline: 1.3264x; 1.0227x over previous
#include <cuda_runtime.h>
#include <cuda_bf16.h>
#include <cstddef>

// Problem constants: N=100000, E=1000000, F=64, H=8, D=8
#define MAXN 100000
#define CLIPV 5.0f
#define INV_SQRT_D 0.35355339059327373f
#define STR 68   // padded smem row stride (floats)

// ---------------- scratch (device globals) -----------------------------------
__device__ float g_Q[(size_t)MAXN * 64];
__device__ float g_K[(size_t)MAXN * 64];
__device__ float g_V[(size_t)MAXN * 64];
// per-node accumulator: 64 floats wV + 8 floats z, stride 72 (288B)
__device__ float g_acc[(size_t)MAXN * 72];

// ---------------- helpers ----------------------------------------------------
__device__ __forceinline__ float clipf(float x) {
    return fminf(fmaxf(x, -CLIPV), CLIPV);
}
__device__ __forceinline__ void red4(float* p, float a, float b, float c, float d) {
    asm volatile("red.global.add.v4.f32 [%0], {%1, %2, %3, %4};"
                 :: "l"(p), "f"(a), "f"(b), "f"(c), "f"(d) : "memory");
}
__device__ __forceinline__ void red1(float* p, float v) {
    asm volatile("red.global.add.f32 [%0], %1;" :: "l"(p), "f"(v) : "memory");
}
// split a float pair into bf16-hi pair and bf16-lo (residual) pair, packed
__device__ __forceinline__ void split2(float x0, float x1, unsigned& hi, unsigned& lo) {
    __nv_bfloat16 h0 = __float2bfloat16_rn(x0);
    __nv_bfloat16 h1 = __float2bfloat16_rn(x1);
    float r0 = x0 - __bfloat162float(h0);
    float r1 = x1 - __bfloat162float(h1);
    __nv_bfloat162 H; H.x = h0; H.y = h1;
    __nv_bfloat162 L; L.x = __float2bfloat16_rn(r0); L.y = __float2bfloat16_rn(r1);
    hi = *reinterpret_cast<unsigned*>(&H);
    lo = *reinterpret_cast<unsigned*>(&L);
}
__device__ __forceinline__ void mma_bf16(float c[4], const unsigned a[4], const unsigned b[2]) {
    asm volatile(
        "mma.sync.aligned.m16n8k16.row.col.f32.bf16.bf16.f32 "
        "{%0,%1,%2,%3}, {%4,%5,%6,%7}, {%8,%9}, {%0,%1,%2,%3};"
        : "+f"(c[0]), "+f"(c[1]), "+f"(c[2]), "+f"(c[3])
        : "r"(a[0]), "r"(a[1]), "r"(a[2]), "r"(a[3]), "r"(b[0]), "r"(b[1]));
}
// load one m16k64 A slice (bf16 hi/lo fragments) from smem tile row base R
__device__ __forceinline__ void load_a_frags(const float* sT, int R, int lq, int lr,
                                             unsigned ah[4][4], unsigned al[4][4]) {
    #pragma unroll
    for (int k = 0; k < 4; k++) {
        const float* base = sT + (size_t)(R + lq) * STR + 16 * k + 2 * lr;
        float2 q0 = *reinterpret_cast<const float2*>(base);
        float2 q1 = *reinterpret_cast<const float2*>(base + 8 * STR);
        float2 q2 = *reinterpret_cast<const float2*>(base + 8);
        float2 q3 = *reinterpret_cast<const float2*>(base + 8 * STR + 8);
        split2(q0.x, q0.y, ah[k][0], al[k][0]);
        split2(q1.x, q1.y, ah[k][1], al[k][1]);
        split2(q2.x, q2.y, ah[k][2], al[k][2]);
        split2(q3.x, q3.y, ah[k][3], al[k][3]);
    }
}

// ---------------- kernel 1: node projections Q,K,V (tensor-core) + acc zero --
__global__ __launch_bounds__(256)
void node_mma_kernel(const float* __restrict__ nf,
                     const float* __restrict__ Wq, const float* __restrict__ bq,
                     const float* __restrict__ Wk, const float* __restrict__ bk,
                     const float* __restrict__ Wv, const float* __restrict__ bv,
                     int N) {
    extern __shared__ float smem[];
    float* sX = smem;               // [128][STR]
    float* sW = smem + 128 * STR;   // [192][STR]

    int tid = threadIdx.x;
    long nBase = (long)blockIdx.x * 128;

    // zero g_acc (grid-stride, vectorized)
    {
        float4 z4 = make_float4(0.f, 0.f, 0.f, 0.f);
        float4* ap = reinterpret_cast<float4*>(g_acc);
        long total4 = (long)N * 18;
        for (long i = (long)blockIdx.x * 256 + tid; i < total4; i += (long)gridDim.x * 256)
            ap[i] = z4;
    }

    for (int i = tid; i < 4096; i += 256) {
        int r = i >> 6, c = i & 63;
        sW[(size_t)r * STR + c]         = Wq[i];
        sW[(size_t)(64 + r) * STR + c]  = Wk[i];
        sW[(size_t)(128 + r) * STR + c] = Wv[i];
    }
    for (int i = tid; i < 128 * 16; i += 256) {
        int r = i >> 4, c4 = i & 15;
        long nn = nBase + r;
        float4 v = make_float4(0.f, 0.f, 0.f, 0.f);
        if (nn < N) v = *reinterpret_cast<const float4*>(nf + nn * 64 + c4 * 4);
        *reinterpret_cast<float4*>(sX + (size_t)r * STR + c4 * 4) = v;
    }
    __syncthreads();

    int w = tid >> 5, l = tid & 31;
    int lq = l >> 2, lr = l & 3;

    unsigned bh[3][4][2], bl[3][4][2];
    #pragma unroll
    for (int t = 0; t < 3; t++) {
        int n = 8 * (3 * w + t) + lq;
        #pragma unroll
        for (int k = 0; k < 4; k++) {
            float2 p0 = *reinterpret_cast<const float2*>(sW + (size_t)n * STR + 16 * k + 2 * lr);
            float2 p1 = *reinterpret_cast<const float2*>(sW + (size_t)n * STR + 16 * k + 2 * lr + 8);
            split2(p0.x, p0.y, bh[t][k][0], bl[t][k][0]);
            split2(p1.x, p1.y, bh[t][k][1], bl[t][k][1]);
        }
    }

    #pragma unroll 1
    for (int mt = 0; mt < 8; mt++) {
        int R = 16 * mt;
        unsigned ah[4][4], al[4][4];
        load_a_frags(sX, R, lq, lr, ah, al);

        #pragma unroll
        for (int t = 0; t < 3; t++) {
            float acc[4] = {0.f, 0.f, 0.f, 0.f};
            #pragma unroll
            for (int k = 0; k < 4; k++) {
                mma_bf16(acc, ah[k], bh[t][k]);
                mma_bf16(acc, ah[k], bl[t][k]);
                mma_bf16(acc, al[k], bh[t][k]);
            }
            int g = 3 * w + t;
            int which = g >> 3;
            int colBase = 8 * (g & 7) + 2 * lr;
            float* outp = (which == 0) ? g_Q : (which == 1) ? g_K : g_V;
            const float* bp = (which == 0) ? bq : (which == 1) ? bk : bv;
            float2 bb = __ldg(reinterpret_cast<const float2*>(bp + colBase));
            long n0 = nBase + R + lq;
            long n1 = n0 + 8;
            if (n0 < N)
                *reinterpret_cast<float2*>(outp + n0 * 64 + colBase) =
                    make_float2(acc[0] + bb.x, acc[1] + bb.y);
            if (n1 < N)
                *reinterpret_cast<float2*>(outp + n1 * 64 + colBase) =
                    make_float2(acc[2] + bb.x, acc[3] + bb.y);
        }
    }
}

// ---------------- kernel 2: edge kernel (quarter of edge range) ---------------
// GEMM part: P = ef @ We^T in smem (in-place over ef tile).
// Epilogue: lane = (edge, head), 2 batches x 2 edges with front-batched loads
// for MLP (src/dst -> K/Q gathers -> compute/store -> V gathers -> reds).
__global__ __launch_bounds__(256)
void edge_mma_kernel(const float* __restrict__ ef,
                     const int* __restrict__ src, const int* __restrict__ dst,
                     const float* __restrict__ We, const float* __restrict__ be,
                     float* __restrict__ e_out, long eOff, int E) {
    extern __shared__ float smem[];
    float* sT = smem;               // ef tile, later P tile [128][STR]
    float* sW = smem + 128 * STR;   // We [64][STR]

    int tid = threadIdx.x;
    long eBase = eOff + (long)blockIdx.x * 128;

    for (int i = tid; i < 4096; i += 256) {
        int r = i >> 6, c = i & 63;
        sW[(size_t)r * STR + c] = We[i];
    }
    for (int i = tid; i < 128 * 16; i += 256) {
        int r = i >> 4, c4 = i & 15;
        long e = eBase + r;
        float4 v = make_float4(0.f, 0.f, 0.f, 0.f);
        if (e < E) v = __ldcs(reinterpret_cast<const float4*>(ef + e * 64 + c4 * 4));
        *reinterpret_cast<float4*>(sT + (size_t)r * STR + c4 * 4) = v;
    }
    __syncthreads();

    int w = tid >> 5, l = tid & 31;
    int lq = l >> 2, lr = l & 3;
    int nhalf = w >> 2;
    int mpair = w & 3;

    unsigned bh[4][4][2], bl[4][4][2];
    #pragma unroll
    for (int t = 0; t < 4; t++) {
        int n = 8 * (4 * nhalf + t) + lq;
        #pragma unroll
        for (int k = 0; k < 4; k++) {
            float2 p0 = *reinterpret_cast<const float2*>(sW + (size_t)n * STR + 16 * k + 2 * lr);
            float2 p1 = *reinterpret_cast<const float2*>(sW + (size_t)n * STR + 16 * k + 2 * lr + 8);
            split2(p0.x, p0.y, bh[t][k][0], bl[t][k][0]);
            split2(p1.x, p1.y, bh[t][k][1], bl[t][k][1]);
        }
    }

    #pragma unroll 1
    for (int mt = 0; mt < 2; mt++) {
        int R = 16 * (2 * mpair + mt);
        unsigned ah[4][4], al[4][4];
        load_a_frags(sT, R, lq, lr, ah, al);
        __syncthreads();   // all A-loads done before P overwrite

        #pragma unroll
        for (int t = 0; t < 4; t++) {
            float acc[4] = {0.f, 0.f, 0.f, 0.f};
            #pragma unroll
            for (int k = 0; k < 4; k++) {
                mma_bf16(acc, ah[k], bh[t][k]);
                mma_bf16(acc, ah[k], bl[t][k]);
                mma_bf16(acc, al[k], bh[t][k]);
            }
            int colBase = 8 * (4 * nhalf + t) + 2 * lr;
            *reinterpret_cast<float2*>(sT + (size_t)(R + lq) * STR + colBase) =
                make_float2(acc[0], acc[1]);
            *reinterpret_cast<float2*>(sT + (size_t)(R + 8 + lq) * STR + colBase) =
                make_float2(acc[2], acc[3]);
        }
    }
    __syncthreads();

    // ---- epilogue: lane = (edge, head); 2 batches of 2 edges, MLP-batched ---
    int h = tid & 7;           // head 0..7
    int eg = tid >> 3;         // 0..31
    float4 b0 = __ldg(reinterpret_cast<const float4*>(be + 8 * h));
    float4 b1 = __ldg(reinterpret_cast<const float4*>(be + 8 * h + 4));

    #pragma unroll
    for (int batch = 0; batch < 2; batch++) {
        int el[2];
        el[0] = batch * 64 + eg;
        el[1] = el[0] + 32;
        long ee[2] = { eBase + el[0], eBase + el[1] };
        bool vld[2] = { ee[0] < E, ee[1] < E };

        int s[2], d[2];
        #pragma unroll
        for (int i = 0; i < 2; i++) {
            s[i] = vld[i] ? __ldcs(src + ee[i]) : 0;
            d[i] = vld[i] ? __ldcs(dst + ee[i]) : 0;
        }

        // front-batched K/Q gathers (up to 8 LDG.128 in flight)
        float4 k0[2], k1[2], q0[2], q1[2];
        #pragma unroll
        for (int i = 0; i < 2; i++) {
            const float4* Kp = reinterpret_cast<const float4*>(g_K + (size_t)s[i] * 64 + 8 * h);
            const float4* Qp = reinterpret_cast<const float4*>(g_Q + (size_t)d[i] * 64 + 8 * h);
            k0[i] = Kp[0]; k1[i] = Kp[1];
            q0[i] = Qp[0]; q1[i] = Qp[1];
        }

        float wv[2];
        #pragma unroll
        for (int i = 0; i < 2; i++) {
            float sc = k0[i].x * q0[i].x + k0[i].y * q0[i].y + k0[i].z * q0[i].z + k0[i].w * q0[i].w
                     + k1[i].x * q1[i].x + k1[i].y * q1[i].y + k1[i].z * q1[i].z + k1[i].w * q1[i].w;
            sc = clipf(sc * INV_SQRT_D);

            const float* Prow = sT + (size_t)el[i] * STR + 8 * h;
            float4 p0 = *reinterpret_cast<const float4*>(Prow);
            float4 p1 = *reinterpret_cast<const float4*>(Prow + 4);
            float4 r0, r1;
            r0.x = sc * (p0.x + b0.x); r0.y = sc * (p0.y + b0.y);
            r0.z = sc * (p0.z + b0.z); r0.w = sc * (p0.w + b0.w);
            r1.x = sc * (p1.x + b1.x); r1.y = sc * (p1.y + b1.y);
            r1.z = sc * (p1.z + b1.z); r1.w = sc * (p1.w + b1.w);
            float ssum = ((r0.x + r0.y) + (r0.z + r0.w)) + ((r1.x + r1.y) + (r1.z + r1.w));
            if (vld[i]) {
                __stcs(reinterpret_cast<float4*>(e_out + (size_t)ee[i] * 64 + 8 * h), r0);
                __stcs(reinterpret_cast<float4*>(e_out + (size_t)ee[i] * 64 + 8 * h + 4), r1);
            }
            wv[i] = __expf(clipf(ssum));
        }

        // front-batched V gathers
        float4 v0[2], v1[2];
        #pragma unroll
        for (int i = 0; i < 2; i++) {
            const float4* Vp = reinterpret_cast<const float4*>(g_V + (size_t)s[i] * 64 + 8 * h);
            v0[i] = Vp[0]; v1[i] = Vp[1];
        }
        #pragma unroll
        for (int i = 0; i < 2; i++) {
            if (vld[i]) {
                float* ap = g_acc + (size_t)d[i] * 72 + 8 * h;
                red4(ap,     v0[i].x * wv[i], v0[i].y * wv[i], v0[i].z * wv[i], v0[i].w * wv[i]);
                red4(ap + 4, v1[i].x * wv[i], v1[i].y * wv[i], v1[i].z * wv[i], v1[i].w * wv[i]);
                red1(g_acc + (size_t)d[i] * 72 + 64 + h, wv[i]);
            }
        }
    }
}

// ---------------- kernel 3: finalize h_out = wV / (z + 1e-6) -----------------
__global__ __launch_bounds__(256)
void finalize_kernel(float* __restrict__ h_out, int N) {
    int t = blockIdx.x * 256 + threadIdx.x;
    if (t >= N * 16) return;
    int n = t >> 4, g = t & 15;
    const float* ap = g_acc + (size_t)n * 72;
    float4 wv = *reinterpret_cast<const float4*>(ap + 4 * g);
    float z = ap[64 + (g >> 1)];
    float inv = 1.0f / (z + 1e-6f);
    float4 r;
    r.x = wv.x * inv; r.y = wv.y * inv; r.z = wv.z * inv; r.w = wv.w * inv;
    __stcs(reinterpret_cast<float4*>(h_out + (size_t)n * 64 + 4 * g), r);
}

// ---------------- launch ------------------------------------------------------
extern "C" void kernel_launch(void* const* d_in, const int* in_sizes, int n_in,
                              void* d_out, int out_size) {
    const float* nf = (const float*)d_in[0];
    const float* ef = (const float*)d_in[1];
    const int*   src = (const int*)d_in[2];
    const int*   dst = (const int*)d_in[3];
    const float* Wq = (const float*)d_in[4];
    const float* bq = (const float*)d_in[5];
    const float* Wk = (const float*)d_in[6];
    const float* bk = (const float*)d_in[7];
    const float* Wv = (const float*)d_in[8];
    const float* bv = (const float*)d_in[9];
    const float* We = (const float*)d_in[10];
    const float* be = (const float*)d_in[11];

    int N = in_sizes[0] / 64;
    int E = in_sizes[2];

    float* h_out = (float*)d_out;                  // [N, 64]
    float* e_out = (float*)d_out + (size_t)N * 64; // [E, 64]

    const int NODE_SMEM = (128 + 192) * STR * 4;   // 87040
    const int EDGE_SMEM = (128 + 64) * STR * 4;    // 52224
    cudaFuncSetAttribute(node_mma_kernel,
                         cudaFuncAttributeMaxDynamicSharedMemorySize, NODE_SMEM);
    cudaFuncSetAttribute(edge_mma_kernel,
                         cudaFuncAttributeMaxDynamicSharedMemorySize, EDGE_SMEM);

    node_mma_kernel<<<(N + 127) / 128, 256, NODE_SMEM>>>(nf, Wq, bq, Wk, bk, Wv, bv, N);

    // 4 quarter launches: profiled capture (absolute launch index 3) lands on e2
    long q = (E + 3) / 4;
    q = ((q + 127) / 128) * 128;  // round to block multiple
    for (int i = 0; i < 4; i++) {
        long off = (long)i * q;
        if (off >= E) break;
        long cnt = (E - off < q) ? (E - off) : q;
        int blocks = (int)((cnt + 127) / 128);
        edge_mma_kernel<<<blocks, 256, EDGE_SMEM>>>(ef, src, dst, We, be, e_out, off, E);
    }

    finalize_kernel<<<((N * 16) + 255) / 256, 256>>>(h_out, N);
}

// round 5
// speedup vs baseline: 1.6236x; 1.2241x over previous
#include <cuda_runtime.h>
#include <cuda_bf16.h>
#include <cstddef>

// Problem constants: N=100000, E=1000000, F=64, H=8, D=8
#define MAXN 100000
#define CLIPV 5.0f
#define INV_SQRT_D 0.35355339059327373f
#define STR 68   // padded smem row stride (floats)

// ---------------- scratch (device globals) -----------------------------------
__device__ float g_Q[(size_t)MAXN * 64];
__device__ float g_K[(size_t)MAXN * 64];
__device__ float g_V[(size_t)MAXN * 64];
// per-node accumulator: 64 floats wV + 8 floats z, stride 72 (288B)
__device__ float g_acc[(size_t)MAXN * 72];

// ---------------- helpers ----------------------------------------------------
__device__ __forceinline__ float clipf(float x) {
    return fminf(fmaxf(x, -CLIPV), CLIPV);
}
__device__ __forceinline__ void red4(float* p, float a, float b, float c, float d) {
    asm volatile("red.global.add.v4.f32 [%0], {%1, %2, %3, %4};"
                 :: "l"(p), "f"(a), "f"(b), "f"(c), "f"(d) : "memory");
}
__device__ __forceinline__ void red1(float* p, float v) {
    asm volatile("red.global.add.f32 [%0], %1;" :: "l"(p), "f"(v) : "memory");
}
// split a float pair into bf16-hi pair and bf16-lo (residual) pair, packed
__device__ __forceinline__ void split2(float x0, float x1, unsigned& hi, unsigned& lo) {
    __nv_bfloat16 h0 = __float2bfloat16_rn(x0);
    __nv_bfloat16 h1 = __float2bfloat16_rn(x1);
    float r0 = x0 - __bfloat162float(h0);
    float r1 = x1 - __bfloat162float(h1);
    __nv_bfloat162 H; H.x = h0; H.y = h1;
    __nv_bfloat162 L; L.x = __float2bfloat16_rn(r0); L.y = __float2bfloat16_rn(r1);
    hi = *reinterpret_cast<unsigned*>(&H);
    lo = *reinterpret_cast<unsigned*>(&L);
}
__device__ __forceinline__ void mma_bf16(float c[4], const unsigned a[4], const unsigned b[2]) {
    asm volatile(
        "mma.sync.aligned.m16n8k16.row.col.f32.bf16.bf16.f32 "
        "{%0,%1,%2,%3}, {%4,%5,%6,%7}, {%8,%9}, {%0,%1,%2,%3};"
        : "+f"(c[0]), "+f"(c[1]), "+f"(c[2]), "+f"(c[3])
        : "r"(a[0]), "r"(a[1]), "r"(a[2]), "r"(a[3]), "r"(b[0]), "r"(b[1]));
}
// load one m16k64 A slice (bf16 hi/lo fragments) from smem tile row base R
__device__ __forceinline__ void load_a_frags(const float* sT, int R, int lq, int lr,
                                             unsigned ah[4][4], unsigned al[4][4]) {
    #pragma unroll
    for (int k = 0; k < 4; k++) {
        const float* base = sT + (size_t)(R + lq) * STR + 16 * k + 2 * lr;
        float2 q0 = *reinterpret_cast<const float2*>(base);
        float2 q1 = *reinterpret_cast<const float2*>(base + 8 * STR);
        float2 q2 = *reinterpret_cast<const float2*>(base + 8);
        float2 q3 = *reinterpret_cast<const float2*>(base + 8 * STR + 8);
        split2(q0.x, q0.y, ah[k][0], al[k][0]);
        split2(q1.x, q1.y, ah[k][1], al[k][1]);
        split2(q2.x, q2.y, ah[k][2], al[k][2]);
        split2(q3.x, q3.y, ah[k][3], al[k][3]);
    }
}

// ---------------- kernel 1: node projections Q,K,V (tensor-core) + acc zero --
__global__ __launch_bounds__(256)
void node_mma_kernel(const float* __restrict__ nf,
                     const float* __restrict__ Wq, const float* __restrict__ bq,
                     const float* __restrict__ Wk, const float* __restrict__ bk,
                     const float* __restrict__ Wv, const float* __restrict__ bv,
                     int N) {
    extern __shared__ float smem[];
    float* sX = smem;               // [128][STR]
    float* sW = smem + 128 * STR;   // [192][STR]

    int tid = threadIdx.x;
    long nBase = (long)blockIdx.x * 128;

    // zero g_acc (grid-stride, vectorized)
    {
        float4 z4 = make_float4(0.f, 0.f, 0.f, 0.f);
        float4* ap = reinterpret_cast<float4*>(g_acc);
        long total4 = (long)N * 18;
        for (long i = (long)blockIdx.x * 256 + tid; i < total4; i += (long)gridDim.x * 256)
            ap[i] = z4;
    }

    for (int i = tid; i < 4096; i += 256) {
        int r = i >> 6, c = i & 63;
        sW[(size_t)r * STR + c]         = Wq[i];
        sW[(size_t)(64 + r) * STR + c]  = Wk[i];
        sW[(size_t)(128 + r) * STR + c] = Wv[i];
    }
    for (int i = tid; i < 128 * 16; i += 256) {
        int r = i >> 4, c4 = i & 15;
        long nn = nBase + r;
        float4 v = make_float4(0.f, 0.f, 0.f, 0.f);
        if (nn < N) v = *reinterpret_cast<const float4*>(nf + nn * 64 + c4 * 4);
        *reinterpret_cast<float4*>(sX + (size_t)r * STR + c4 * 4) = v;
    }
    __syncthreads();

    int w = tid >> 5, l = tid & 31;
    int lq = l >> 2, lr = l & 3;

    unsigned bh[3][4][2], bl[3][4][2];
    #pragma unroll
    for (int t = 0; t < 3; t++) {
        int n = 8 * (3 * w + t) + lq;
        #pragma unroll
        for (int k = 0; k < 4; k++) {
            float2 p0 = *reinterpret_cast<const float2*>(sW + (size_t)n * STR + 16 * k + 2 * lr);
            float2 p1 = *reinterpret_cast<const float2*>(sW + (size_t)n * STR + 16 * k + 2 * lr + 8);
            split2(p0.x, p0.y, bh[t][k][0], bl[t][k][0]);
            split2(p1.x, p1.y, bh[t][k][1], bl[t][k][1]);
        }
    }

    #pragma unroll 1
    for (int mt = 0; mt < 8; mt++) {
        int R = 16 * mt;
        unsigned ah[4][4], al[4][4];
        load_a_frags(sX, R, lq, lr, ah, al);

        #pragma unroll
        for (int t = 0; t < 3; t++) {
            float acc[4] = {0.f, 0.f, 0.f, 0.f};
            #pragma unroll
            for (int k = 0; k < 4; k++) {
                mma_bf16(acc, ah[k], bh[t][k]);
                mma_bf16(acc, ah[k], bl[t][k]);
                mma_bf16(acc, al[k], bh[t][k]);
            }
            int g = 3 * w + t;
            int which = g >> 3;
            int colBase = 8 * (g & 7) + 2 * lr;
            float* outp = (which == 0) ? g_Q : (which == 1) ? g_K : g_V;
            const float* bp = (which == 0) ? bq : (which == 1) ? bk : bv;
            float2 bb = __ldg(reinterpret_cast<const float2*>(bp + colBase));
            long n0 = nBase + R + lq;
            long n1 = n0 + 8;
            if (n0 < N)
                *reinterpret_cast<float2*>(outp + n0 * 64 + colBase) =
                    make_float2(acc[0] + bb.x, acc[1] + bb.y);
            if (n1 < N)
                *reinterpret_cast<float2*>(outp + n1 * 64 + colBase) =
                    make_float2(acc[2] + bb.x, acc[3] + bb.y);
        }
    }
}

// ---------------- kernel 2: edge kernel (quarter of edge range) ---------------
// Restructured for occupancy (target 3 blocks/SM):
//  - We pre-split into MMA-ready packed bf16 hi/lo fragments in smem (16KB,
//    one uint4 per (ntile,k,lane)) -> no 64-reg B cache, no split2 recompute.
//  - warp w owns m-tile w (rows 16w..16w+15) for BOTH A-load and P-store ->
//    no mid-GEMM __syncthreads.
//  - epilogue unchanged from round 4 (lane=(edge,head), 2-edge MLP batches).
__global__ __launch_bounds__(256, 3)
void edge_mma_kernel(const float* __restrict__ ef,
                     const int* __restrict__ src, const int* __restrict__ dst,
                     const float* __restrict__ We, const float* __restrict__ be,
                     float* __restrict__ e_out, long eOff, int E) {
    extern __shared__ float smem[];
    float* sT = smem;                                   // ef tile -> P tile [128][STR]
    uint4* sB = reinterpret_cast<uint4*>(smem + 128 * STR);  // [8][4][32] packed frags

    int tid = threadIdx.x;
    long eBase = eOff + (long)blockIdx.x * 128;

    // pack B fragments: item i = ((t*4 + k)*32 + l)
    for (int i = tid; i < 1024; i += 256) {
        int t = i >> 7, k = (i >> 5) & 3, l = i & 31;
        int lq = l >> 2, lr = l & 3;
        const float* wr = We + (size_t)(8 * t + lq) * 64 + 16 * k + 2 * lr;
        float w0 = __ldg(wr),     w1 = __ldg(wr + 1);
        float w8 = __ldg(wr + 8), w9 = __ldg(wr + 9);
        unsigned h0, l0, h1, l1;
        split2(w0, w1, h0, l0);
        split2(w8, w9, h1, l1);
        sB[i] = make_uint4(h0, h1, l0, l1);
    }
    // stage ef tile
    for (int i = tid; i < 128 * 16; i += 256) {
        int r = i >> 4, c4 = i & 15;
        long e = eBase + r;
        float4 v = make_float4(0.f, 0.f, 0.f, 0.f);
        if (e < E) v = __ldcs(reinterpret_cast<const float4*>(ef + e * 64 + c4 * 4));
        *reinterpret_cast<float4*>(sT + (size_t)r * STR + c4 * 4) = v;
    }
    __syncthreads();

    int w = tid >> 5, l = tid & 31;
    int lq = l >> 2, lr = l & 3;
    int R = 16 * w;   // warp-private m-tile rows

    {
        unsigned ah[4][4], al[4][4];
        load_a_frags(sT, R, lq, lr, ah, al);
        // in-place P store is safe: A already in regs, rows are warp-private

        #pragma unroll 2
        for (int t = 0; t < 8; t++) {
            float acc[4] = {0.f, 0.f, 0.f, 0.f};
            #pragma unroll
            for (int k = 0; k < 4; k++) {
                uint4 b = sB[(t * 4 + k) * 32 + l];
                unsigned bh[2] = { b.x, b.y };
                unsigned bl[2] = { b.z, b.w };
                mma_bf16(acc, ah[k], bh);
                mma_bf16(acc, ah[k], bl);
                mma_bf16(acc, al[k], bh);
            }
            int colBase = 8 * t + 2 * lr;
            *reinterpret_cast<float2*>(sT + (size_t)(R + lq) * STR + colBase) =
                make_float2(acc[0], acc[1]);
            *reinterpret_cast<float2*>(sT + (size_t)(R + 8 + lq) * STR + colBase) =
                make_float2(acc[2], acc[3]);
        }
    }
    __syncthreads();

    // ---- epilogue: lane = (edge, head); 2 batches of 2 edges, MLP-batched ---
    int h = tid & 7;           // head 0..7
    int eg = tid >> 3;         // 0..31
    float4 b0 = __ldg(reinterpret_cast<const float4*>(be + 8 * h));
    float4 b1 = __ldg(reinterpret_cast<const float4*>(be + 8 * h + 4));

    #pragma unroll
    for (int batch = 0; batch < 2; batch++) {
        int el[2];
        el[0] = batch * 64 + eg;
        el[1] = el[0] + 32;
        long ee[2] = { eBase + el[0], eBase + el[1] };
        bool vld[2] = { ee[0] < E, ee[1] < E };

        int s[2], d[2];
        #pragma unroll
        for (int i = 0; i < 2; i++) {
            s[i] = vld[i] ? __ldcs(src + ee[i]) : 0;
            d[i] = vld[i] ? __ldcs(dst + ee[i]) : 0;
        }

        float4 k0[2], k1[2], q0[2], q1[2];
        #pragma unroll
        for (int i = 0; i < 2; i++) {
            const float4* Kp = reinterpret_cast<const float4*>(g_K + (size_t)s[i] * 64 + 8 * h);
            const float4* Qp = reinterpret_cast<const float4*>(g_Q + (size_t)d[i] * 64 + 8 * h);
            k0[i] = Kp[0]; k1[i] = Kp[1];
            q0[i] = Qp[0]; q1[i] = Qp[1];
        }

        float wv[2];
        #pragma unroll
        for (int i = 0; i < 2; i++) {
            float sc = k0[i].x * q0[i].x + k0[i].y * q0[i].y + k0[i].z * q0[i].z + k0[i].w * q0[i].w
                     + k1[i].x * q1[i].x + k1[i].y * q1[i].y + k1[i].z * q1[i].z + k1[i].w * q1[i].w;
            sc = clipf(sc * INV_SQRT_D);

            const float* Prow = sT + (size_t)el[i] * STR + 8 * h;
            float4 p0 = *reinterpret_cast<const float4*>(Prow);
            float4 p1 = *reinterpret_cast<const float4*>(Prow + 4);
            float4 r0, r1;
            r0.x = sc * (p0.x + b0.x); r0.y = sc * (p0.y + b0.y);
            r0.z = sc * (p0.z + b0.z); r0.w = sc * (p0.w + b0.w);
            r1.x = sc * (p1.x + b1.x); r1.y = sc * (p1.y + b1.y);
            r1.z = sc * (p1.z + b1.z); r1.w = sc * (p1.w + b1.w);
            float ssum = ((r0.x + r0.y) + (r0.z + r0.w)) + ((r1.x + r1.y) + (r1.z + r1.w));
            if (vld[i]) {
                __stcs(reinterpret_cast<float4*>(e_out + (size_t)ee[i] * 64 + 8 * h), r0);
                __stcs(reinterpret_cast<float4*>(e_out + (size_t)ee[i] * 64 + 8 * h + 4), r1);
            }
            wv[i] = __expf(clipf(ssum));
        }

        float4 v0[2], v1[2];
        #pragma unroll
        for (int i = 0; i < 2; i++) {
            const float4* Vp = reinterpret_cast<const float4*>(g_V + (size_t)s[i] * 64 + 8 * h);
            v0[i] = Vp[0]; v1[i] = Vp[1];
        }
        #pragma unroll
        for (int i = 0; i < 2; i++) {
            if (vld[i]) {
                float* ap = g_acc + (size_t)d[i] * 72 + 8 * h;
                red4(ap,     v0[i].x * wv[i], v0[i].y * wv[i], v0[i].z * wv[i], v0[i].w * wv[i]);
                red4(ap + 4, v1[i].x * wv[i], v1[i].y * wv[i], v1[i].z * wv[i], v1[i].w * wv[i]);
                red1(g_acc + (size_t)d[i] * 72 + 64 + h, wv[i]);
            }
        }
    }
}

// ---------------- kernel 3: finalize h_out = wV / (z + 1e-6) -----------------
__global__ __launch_bounds__(256)
void finalize_kernel(float* __restrict__ h_out, int N) {
    int t = blockIdx.x * 256 + threadIdx.x;
    if (t >= N * 16) return;
    int n = t >> 4, g = t & 15;
    const float* ap = g_acc + (size_t)n * 72;
    float4 wv = *reinterpret_cast<const float4*>(ap + 4 * g);
    float z = ap[64 + (g >> 1)];
    float inv = 1.0f / (z + 1e-6f);
    float4 r;
    r.x = wv.x * inv; r.y = wv.y * inv; r.z = wv.z * inv; r.w = wv.w * inv;
    __stcs(reinterpret_cast<float4*>(h_out + (size_t)n * 64 + 4 * g), r);
}

// ---------------- launch ------------------------------------------------------
extern "C" void kernel_launch(void* const* d_in, const int* in_sizes, int n_in,
                              void* d_out, int out_size) {
    const float* nf = (const float*)d_in[0];
    const float* ef = (const float*)d_in[1];
    const int*   src = (const int*)d_in[2];
    const int*   dst = (const int*)d_in[3];
    const float* Wq = (const float*)d_in[4];
    const float* bq = (const float*)d_in[5];
    const float* Wk = (const float*)d_in[6];
    const float* bk = (const float*)d_in[7];
    const float* Wv = (const float*)d_in[8];
    const float* bv = (const float*)d_in[9];
    const float* We = (const float*)d_in[10];
    const float* be = (const float*)d_in[11];

    int N = in_sizes[0] / 64;
    int E = in_sizes[2];

    float* h_out = (float*)d_out;                  // [N, 64]
    float* e_out = (float*)d_out + (size_t)N * 64; // [E, 64]

    const int NODE_SMEM = (128 + 192) * STR * 4;          // 87040
    const int EDGE_SMEM = 128 * STR * 4 + 8 * 4 * 32 * 16; // 34816 + 16384 = 51200
    cudaFuncSetAttribute(node_mma_kernel,
                         cudaFuncAttributeMaxDynamicSharedMemorySize, NODE_SMEM);
    cudaFuncSetAttribute(edge_mma_kernel,
                         cudaFuncAttributeMaxDynamicSharedMemorySize, EDGE_SMEM);

    node_mma_kernel<<<(N + 127) / 128, 256, NODE_SMEM>>>(nf, Wq, bq, Wk, bk, Wv, bv, N);

    // 4 quarter launches: profiled capture (absolute launch index 3) lands on e2
    long q = (E + 3) / 4;
    q = ((q + 127) / 128) * 128;  // round to block multiple
    for (int i = 0; i < 4; i++) {
        long off = (long)i * q;
        if (off >= E) break;
        long cnt = (E - off < q) ? (E - off) : q;
        int blocks = (int)((cnt + 127) / 128);
        edge_mma_kernel<<<blocks, 256, EDGE_SMEM>>>(ef, src, dst, We, be, e_out, off, E);
    }

    finalize_kernel<<<((N * 16) + 255) / 256, 256>>>(h_out, N);
}